// round 6
// baseline (speedup 1.0000x reference)
#include <cuda_runtime.h>
#include <cuda_bf16.h>
#include <cstdint>

// Problem constants (fixed by setup_inputs)
#define DIM   128
#define LMAX  60000
#define CMAX  30000
#define EMAX  360000
#define NITER 8

// ---------------- scratch (device globals; no allocations allowed) ----------
__device__ float g_l2c_msg[(size_t)LMAX * DIM];
__device__ float g_c2l_msg[(size_t)CMAX * DIM];
__device__ float g_l2l_msg[(size_t)LMAX * DIM];
__device__ float g_aggr_c [(size_t)CMAX * DIM];
__device__ float g_aggr_l [(size_t)LMAX * DIM];
// CSR scratch
__device__ int g_cnt_c[CMAX];
__device__ int g_cnt_l[LMAX];
__device__ int g_off_c[CMAX + 1];
__device__ int g_off_l[LMAX + 1];
__device__ int g_cur_c[CMAX];
__device__ int g_cur_l[LMAX];
__device__ int g_src_c[EMAX];
__device__ int g_src_l[EMAX];
// pre-split bf16 weight planes (u32 = 2 bf16), fragment-ordered
#define WSPLIT_TOTAL 172032
__device__ uint32_t g_whi[WSPLIT_TOTAL];
__device__ uint32_t g_wlo[WSPLIT_TOTAL];

// ======================= helpers =============================================
__device__ __forceinline__ uint32_t smem_u32(const void* p) {
    uint32_t a;
    asm("{ .reg .u64 t; cvta.to.shared.u64 t, %1; cvt.u32.u64 %0, t; }"
        : "=r"(a) : "l"(p));
    return a;
}

__device__ __forceinline__ uint32_t pack_bf16(float lo, float hi) {
    uint32_t r;
    asm("cvt.rn.bf16x2.f32 %0, %1, %2;" : "=r"(r) : "f"(hi), "f"(lo));
    return r;
}

__device__ __forceinline__ void split2(float x, float y, uint32_t& hi, uint32_t& lo) {
    uint32_t h = pack_bf16(x, y);
    float hx = __uint_as_float(h << 16);
    float hy = __uint_as_float(h & 0xffff0000u);
    hi = h;
    lo = pack_bf16(x - hx, y - hy);
}

__device__ __forceinline__ void cp16(uint32_t dst, const void* src) {
    asm volatile("cp.async.ca.shared.global [%0], [%1], 16;"
                 :: "r"(dst), "l"(src) : "memory");
}
#define CP_COMMIT() asm volatile("cp.async.commit_group;" ::: "memory")
#define CP_WAIT0()  asm volatile("cp.async.wait_group 0;" ::: "memory")
#define CP_WAIT1()  asm volatile("cp.async.wait_group 1;" ::: "memory")

__device__ __forceinline__ void mma_bf16(float* d, const uint32_t* a,
                                         uint32_t b0, uint32_t b1) {
    asm volatile(
        "mma.sync.aligned.m16n8k16.row.col.f32.bf16.bf16.f32 "
        "{%0,%1,%2,%3}, {%4,%5,%6,%7}, {%8,%9}, {%0,%1,%2,%3};"
        : "+f"(d[0]), "+f"(d[1]), "+f"(d[2]), "+f"(d[3])
        : "r"(a[0]), "r"(a[1]), "r"(a[2]), "r"(a[3]), "r"(b0), "r"(b1));
}

// swizzled u32 index within 128x8 (or 32x8) plane
#define IDX(r, q) ((((r) << 3)) | ((q) ^ ((r) & 7)))

__device__ __forceinline__ float fsigmoid(float x) { return 1.f / (1.f + __expf(-x)); }
__device__ __forceinline__ float ftanh(float x) {
    float t = __expf(2.f * fabsf(x));
    float r = 1.f - 2.f / (t + 1.f);
    return copysignf(r, x);
}

// ======================= weight pre-split (fragment-ordered) =================
// Per 128-row n-group and K16 chunk: 1024 u32 per plane; consumer lane reads
// uint4 at lane*32 + ((c ^ (lane&7))<<2) giving n-tiles {2c, 2c+1} fragments.
__global__ void split_w(const float* __restrict__ W, uint32_t* __restrict__ hi,
                        uint32_t* __restrict__ lo, int total_pairs, int kp)
{
    int i = blockIdx.x * 256 + threadIdx.x;
    if (i >= total_pairs) return;
    int R = i / kp, p = i - R * kp;
    float2 f = ((const float2*)W)[i];
    uint32_t h, l;
    split2(f.x, f.y, h, l);
    int ngroup = R >> 7, n = R & 127;
    int ch = p >> 3, q = p & 7;
    int nt = n >> 3, l4 = n & 7;
    int region = l4 * 4 + (q & 3);
    int idx = region * 32 + (((nt >> 1) ^ (region & 7)) << 2) + ((nt & 1) << 1) + (q >> 2);
    size_t base = ((size_t)(ngroup * (kp >> 3) + ch)) << 10;
    hi[base + idx] = h;
    lo[base + idx] = l;
}

// ======================= MMA chunk (128-row tile, 128 cols) ==================
// buffer layout (u32): [Ah 1024][Al 1024][Bh 1024][Bl 1024] = 16KB
__device__ __forceinline__ void mma_chunk_v(const uint32_t* __restrict__ sb,
                                            float acc[16][4], int lane, int wid)
{
    const uint32_t* Ah = sb;
    const uint32_t* Al = sb + 1024;
    const int r = wid * 16 + (lane >> 2);
    const int q = lane & 3;
    uint32_t ah[4], al[4];
    ah[0] = Ah[IDX(r, q)];     ah[1] = Ah[IDX(r + 8, q)];
    ah[2] = Ah[IDX(r, q + 4)]; ah[3] = Ah[IDX(r + 8, q + 4)];
    al[0] = Al[IDX(r, q)];     al[1] = Al[IDX(r + 8, q)];
    al[2] = Al[IDX(r, q + 4)]; al[3] = Al[IDX(r + 8, q + 4)];
    const uint32_t* Bh = sb + 2048 + lane * 32;
    const uint32_t* Bl = Bh + 1024;
#pragma unroll
    for (int c = 0; c < 8; c++) {
        const int sw = ((c ^ (lane & 7)) << 2);
        uint4 vh = *(const uint4*)(Bh + sw);
        uint4 vl = *(const uint4*)(Bl + sw);
        mma_bf16(acc[2 * c],     ah, vh.x, vh.y);
        mma_bf16(acc[2 * c],     al, vh.x, vh.y);
        mma_bf16(acc[2 * c],     ah, vl.x, vl.y);
        mma_bf16(acc[2 * c + 1], ah, vh.z, vh.w);
        mma_bf16(acc[2 * c + 1], al, vh.z, vh.w);
        mma_bf16(acc[2 * c + 1], ah, vl.z, vl.w);
    }
}

__device__ __forceinline__ void mma_chunk_areg_v(const uint32_t* __restrict__ sb,
                                                 const float a1[16][4], float acc[16][4],
                                                 int c2, int lane)
{
    uint32_t ah[4], al[4];
    split2(a1[2 * c2][0],     a1[2 * c2][1],     ah[0], al[0]);
    split2(a1[2 * c2][2],     a1[2 * c2][3],     ah[1], al[1]);
    split2(a1[2 * c2 + 1][0], a1[2 * c2 + 1][1], ah[2], al[2]);
    split2(a1[2 * c2 + 1][2], a1[2 * c2 + 1][3], ah[3], al[3]);
    const uint32_t* Bh = sb + 2048 + lane * 32;
    const uint32_t* Bl = Bh + 1024;
#pragma unroll
    for (int c = 0; c < 8; c++) {
        const int sw = ((c ^ (lane & 7)) << 2);
        uint4 vh = *(const uint4*)(Bh + sw);
        uint4 vl = *(const uint4*)(Bl + sw);
        mma_bf16(acc[2 * c],     ah, vh.x, vh.y);
        mma_bf16(acc[2 * c],     al, vh.x, vh.y);
        mma_bf16(acc[2 * c],     ah, vl.x, vl.y);
        mma_bf16(acc[2 * c + 1], ah, vh.z, vh.w);
        mma_bf16(acc[2 * c + 1], al, vh.z, vh.w);
        mma_bf16(acc[2 * c + 1], ah, vl.z, vl.w);
    }
}

// ======================= fused 2-layer MLP ===================================
__global__ __launch_bounds__(256, 1)
void mlp2_bf3(const float* __restrict__ A0,
              const uint32_t* __restrict__ W0h, const uint32_t* __restrict__ W0l,
              const float* __restrict__ b0,
              const uint32_t* __restrict__ W1h, const uint32_t* __restrict__ W1l,
              const float* __restrict__ b1,
              float* __restrict__ out, int N, int perm)
{
    __shared__ __align__(16) uint32_t sm[3 * 4096];
    __shared__ float sb0[128];

    const int t = threadIdx.x, lane = t & 31, wid = t >> 5;
    const int m0 = blockIdx.x * 128;

    if (t < 128) sb0[t] = b0[t];

    float acc1[16][4];
#pragma unroll
    for (int i = 0; i < 16; i++)
#pragma unroll
        for (int j = 0; j < 4; j++) acc1[i][j] = 0.f;

    const int arow_l = t >> 1;
    const int afl = (t & 1) * 8;
    const int grow = m0 + arow_l;
    int arow = (perm ? (grow ^ 1) : grow);
    if (grow >= N) arow = 0;
    float4 ra0, ra1;

    const int wrow = t & 127;
    const int wpl = t >> 7;
    const uint32_t* w0p = wpl ? W0l : W0h;
    const uint32_t* w1p = wpl ? W1l : W1h;

#define LDA1(ch) do { \
        const float* p = A0 + (size_t)arow * 128 + ((ch) << 4) + afl; \
        ra0 = *(const float4*)p; ra1 = *(const float4*)(p + 4); \
    } while (0)
#define STA1(buf) do { \
        uint32_t* Ah = sm + (buf) * 4096; \
        uint32_t* Al = Ah + 1024; \
        uint32_t h0, l0; \
        split2(ra0.x, ra0.y, h0, l0); Ah[IDX(arow_l, (afl >> 1) + 0)] = h0; Al[IDX(arow_l, (afl >> 1) + 0)] = l0; \
        split2(ra0.z, ra0.w, h0, l0); Ah[IDX(arow_l, (afl >> 1) + 1)] = h0; Al[IDX(arow_l, (afl >> 1) + 1)] = l0; \
        split2(ra1.x, ra1.y, h0, l0); Ah[IDX(arow_l, (afl >> 1) + 2)] = h0; Al[IDX(arow_l, (afl >> 1) + 2)] = l0; \
        split2(ra1.z, ra1.w, h0, l0); Ah[IDX(arow_l, (afl >> 1) + 3)] = h0; Al[IDX(arow_l, (afl >> 1) + 3)] = l0; \
    } while (0)
#define CPW1(wb, ch, buf) do { \
        const uint32_t* gp = (wb) + ((size_t)(ch) << 10) + wrow * 8; \
        uint32_t daddr = smem_u32(sm + (buf) * 4096 + (2 + wpl) * 1024 + wrow * 8); \
        cp16(daddr, gp); cp16(daddr + 16, gp + 4); \
    } while (0)

    // ---- stage 1 ----
    LDA1(0); CPW1(w0p, 0, 0); CP_COMMIT(); STA1(0);
    LDA1(1); CPW1(w0p, 1, 1); CP_COMMIT(); STA1(1); CP_WAIT1();
    __syncthreads();
    for (int ch = 0; ch < 8; ch++) {
        mma_chunk_v(sm + (ch % 3) * 4096, acc1, lane, wid);
        if (ch + 1 < 8) {
            if (ch + 2 < 8) {
                LDA1(ch + 2); CPW1(w0p, ch + 2, (ch + 2) % 3); CP_COMMIT();
                STA1((ch + 2) % 3);
                CP_WAIT1();
            } else CP_WAIT0();
            __syncthreads();
        }
    }
    __syncthreads();

#pragma unroll
    for (int nt = 0; nt < 16; nt++) {
        const int col = nt * 8 + 2 * (lane & 3);
        float bx = sb0[col], by = sb0[col + 1];
        acc1[nt][0] = fmaxf(acc1[nt][0] + bx, 0.f);
        acc1[nt][1] = fmaxf(acc1[nt][1] + by, 0.f);
        acc1[nt][2] = fmaxf(acc1[nt][2] + bx, 0.f);
        acc1[nt][3] = fmaxf(acc1[nt][3] + by, 0.f);
    }

    float acc2[16][4];
#pragma unroll
    for (int i = 0; i < 16; i++)
#pragma unroll
        for (int j = 0; j < 4; j++) acc2[i][j] = 0.f;

    CPW1(w1p, 0, 0); CP_COMMIT();
    CPW1(w1p, 1, 1); CP_COMMIT(); CP_WAIT1();
    __syncthreads();
    for (int ch = 0; ch < 8; ch++) {
        mma_chunk_areg_v(sm + (ch % 3) * 4096, acc1, acc2, ch, lane);
        if (ch + 1 < 8) {
            if (ch + 2 < 8) { CPW1(w1p, ch + 2, (ch + 2) % 3); CP_COMMIT(); CP_WAIT1(); }
            else CP_WAIT0();
            __syncthreads();
        }
    }

    const int r0 = m0 + wid * 16 + (lane >> 2);
#pragma unroll
    for (int nt = 0; nt < 16; nt++) {
        const int col = nt * 8 + 2 * (lane & 3);
        float bx = b1[col], by = b1[col + 1];
        if (r0 < N)
            *(float2*)(out + (size_t)r0 * 128 + col) =
                make_float2(acc2[nt][0] + bx, acc2[nt][1] + by);
        if (r0 + 8 < N)
            *(float2*)(out + (size_t)(r0 + 8) * 128 + col) =
                make_float2(acc2[nt][2] + bx, acc2[nt][3] + by);
    }
#undef LDA1
#undef STA1
#undef CPW1
}

// ======================= fused GRU ===========================================
// h_next = GRU(gi = concat(giA0,giA1) @ Wih^T + bih, gh = h @ Whh^T + bhh, h)
// CTA: 32 rows x 384 cols. Warp w owns n-tiles {2w,2w+1} of each gate group.
// chunk buffer (u32): [Ah 256][Al 256][Bh 3072][Bl 3072] = 6656 u32 = 26KB
#define GCH 6656
#define GRU_DSMEM (3 * GCH * 4)

__global__ __launch_bounds__(256)
void gru_fused(const float* __restrict__ giA0, const float* __restrict__ giA1,
               int Ki,
               const uint32_t* __restrict__ Wih_h, const uint32_t* __restrict__ Wih_l,
               const float* __restrict__ bih,
               const uint32_t* __restrict__ Whh_h, const uint32_t* __restrict__ Whh_l,
               const float* __restrict__ bhh,
               const float* __restrict__ hprev, float* __restrict__ hnext, int N)
{
    extern __shared__ __align__(16) uint32_t dsm[];
    __shared__ float sbi[384], sbh[384];

    const int t = threadIdx.x, lane = t & 31, wid = t >> 5;
    const int m0 = blockIdx.x * 32;
    for (int i = t; i < 384; i += 256) { sbi[i] = bih[i]; sbh[i] = bhh[i]; }

    const int nch_i = Ki >> 4;
    const int nch_tot = nch_i + 8;

    float acc_sum[2][6][4];
    float acc_hn[2][2][4];
#pragma unroll
    for (int a = 0; a < 2; a++) {
#pragma unroll
        for (int b = 0; b < 6; b++)
#pragma unroll
            for (int c = 0; c < 4; c++) acc_sum[a][b][c] = 0.f;
#pragma unroll
        for (int b = 0; b < 2; b++)
#pragma unroll
            for (int c = 0; c < 4; c++) acc_hn[a][b][c] = 0.f;
    }

    // A loader mapping: thread t -> row t>>3 (0..31), float-pair q = t&7
    const int arow_l = t >> 3;
    const int aq = t & 7;
    int arow = m0 + arow_l;
    if (arow >= N) arow = 0;
    float2 av;

    // B loader mapping
    const int wrow = t & 127;
    const int wpl = t >> 7;

#define GLDA(ch) do { \
        const float* src; int kcol; \
        if ((ch) < nch_i) { int kc = (ch) << 4; src = (kc < 128) ? giA0 : giA1; kcol = kc & 127; } \
        else { src = hprev; kcol = ((ch) - nch_i) << 4; } \
        av = *(const float2*)(src + (size_t)arow * 128 + kcol + aq * 2); \
    } while (0)

#define GSTA(buf) do { \
        uint32_t* Ah = dsm + (buf) * GCH; \
        uint32_t h0, l0; \
        split2(av.x, av.y, h0, l0); \
        Ah[IDX(arow_l, aq)] = h0; Ah[256 + IDX(arow_l, aq)] = l0; \
    } while (0)

#define GCPB(ch, buf) do { \
        const int gi_p = (ch) < nch_i; \
        const int chl = gi_p ? (ch) : (ch) - nch_i; \
        const int nchk = gi_p ? nch_i : 8; \
        const uint32_t* pl = wpl ? (gi_p ? Wih_l : Whh_l) : (gi_p ? Wih_h : Whh_h); \
        uint32_t dbase = smem_u32(dsm + (buf) * GCH + 512 + wpl * 3072 + wrow * 8); \
        _Pragma("unroll") \
        for (int g = 0; g < 3; g++) { \
            const uint32_t* gp = pl + ((size_t)(g * nchk + chl) << 10) + wrow * 8; \
            cp16(dbase + g * 4096, gp); cp16(dbase + g * 4096 + 16, gp + 4); \
        } \
    } while (0)

    // prologue
    GLDA(0); GCPB(0, 0); CP_COMMIT(); GSTA(0);
    GLDA(1); GCPB(1, 1); CP_COMMIT(); GSTA(1); CP_WAIT1();
    __syncthreads();

    const int q = lane & 3;
    const int swb = ((wid ^ (lane & 7)) << 2) + lane * 32;

    for (int ch = 0; ch < nch_tot; ch++) {
        const uint32_t* sb = dsm + (ch % 3) * GCH;
        const int gh_p = ch >= nch_i;
        // A fragments (broadcast across warps)
        uint32_t ah0[4], al0[4], ah1[4], al1[4];
        {
            const uint32_t* Ah = sb;
            const uint32_t* Al = sb + 256;
            int r = lane >> 2;
            ah0[0] = Ah[IDX(r, q)];      ah0[1] = Ah[IDX(r + 8, q)];
            ah0[2] = Ah[IDX(r, q + 4)];  ah0[3] = Ah[IDX(r + 8, q + 4)];
            al0[0] = Al[IDX(r, q)];      al0[1] = Al[IDX(r + 8, q)];
            al0[2] = Al[IDX(r, q + 4)];  al0[3] = Al[IDX(r + 8, q + 4)];
            r += 16;
            ah1[0] = Ah[IDX(r, q)];      ah1[1] = Ah[IDX(r + 8, q)];
            ah1[2] = Ah[IDX(r, q + 4)];  ah1[3] = Ah[IDX(r + 8, q + 4)];
            al1[0] = Al[IDX(r, q)];      al1[1] = Al[IDX(r + 8, q)];
            al1[2] = Al[IDX(r, q + 4)];  al1[3] = Al[IDX(r + 8, q + 4)];
        }
        const uint32_t* B = sb + 512;
#pragma unroll
        for (int g = 0; g < 3; g++) {
            uint4 vh = *(const uint4*)(B + g * 1024 + swb);
            uint4 vl = *(const uint4*)(B + 3072 + g * 1024 + swb);
            float* d00;
            float* d01;
            float* d10;
            float* d11;
            if (gh_p && g == 2) {
                d00 = acc_hn[0][0]; d01 = acc_hn[0][1];
                d10 = acc_hn[1][0]; d11 = acc_hn[1][1];
            } else {
                d00 = acc_sum[0][g * 2];     d01 = acc_sum[0][g * 2 + 1];
                d10 = acc_sum[1][g * 2];     d11 = acc_sum[1][g * 2 + 1];
            }
            // term-major ordering: RAW gap of 4 MMAs
            mma_bf16(d00, ah0, vh.x, vh.y);
            mma_bf16(d01, ah0, vh.z, vh.w);
            mma_bf16(d10, ah1, vh.x, vh.y);
            mma_bf16(d11, ah1, vh.z, vh.w);
            mma_bf16(d00, al0, vh.x, vh.y);
            mma_bf16(d01, al0, vh.z, vh.w);
            mma_bf16(d10, al1, vh.x, vh.y);
            mma_bf16(d11, al1, vh.z, vh.w);
            mma_bf16(d00, ah0, vl.x, vl.y);
            mma_bf16(d01, ah0, vl.z, vl.w);
            mma_bf16(d10, ah1, vl.x, vl.y);
            mma_bf16(d11, ah1, vl.z, vl.w);
        }
        if (ch + 1 < nch_tot) {
            if (ch + 2 < nch_tot) {
                GLDA(ch + 2); GCPB(ch + 2, (ch + 2) % 3); CP_COMMIT();
                GSTA((ch + 2) % 3);
                CP_WAIT1();
            } else CP_WAIT0();
            __syncthreads();
        }
    }

    // ---- GRU epilogue ----
#pragma unroll
    for (int mt = 0; mt < 2; mt++) {
#pragma unroll
        for (int tt = 0; tt < 2; tt++) {
            const int j = (wid * 2 + tt) * 8 + 2 * (lane & 3);
            float br0 = sbi[j]       + sbh[j];
            float br1 = sbi[j + 1]   + sbh[j + 1];
            float bz0 = sbi[128 + j]     + sbh[128 + j];
            float bz1 = sbi[128 + j + 1] + sbh[128 + j + 1];
            float bi0 = sbi[256 + j],     bi1 = sbi[256 + j + 1];
            float bh0 = sbh[256 + j],     bh1 = sbh[256 + j + 1];
#pragma unroll
            for (int p = 0; p < 2; p++) {
                const int row = m0 + mt * 16 + (lane >> 2) + p * 8;
                if (row < N) {
                    float2 h2 = *(const float2*)(hprev + (size_t)row * 128 + j);
                    float r0 = fsigmoid(acc_sum[mt][tt][2 * p]     + br0);
                    float r1 = fsigmoid(acc_sum[mt][tt][2 * p + 1] + br1);
                    float z0 = fsigmoid(acc_sum[mt][2 + tt][2 * p]     + bz0);
                    float z1 = fsigmoid(acc_sum[mt][2 + tt][2 * p + 1] + bz1);
                    float n0 = ftanh(acc_sum[mt][4 + tt][2 * p]     + bi0 +
                                     r0 * (acc_hn[mt][tt][2 * p]     + bh0));
                    float n1 = ftanh(acc_sum[mt][4 + tt][2 * p + 1] + bi1 +
                                     r1 * (acc_hn[mt][tt][2 * p + 1] + bh1));
                    float2 o;
                    o.x = (1.f - z0) * n0 + z0 * h2.x;
                    o.y = (1.f - z1) * n1 + z1 * h2.y;
                    *(float2*)(hnext + (size_t)row * 128 + j) = o;
                }
            }
        }
    }
#undef GLDA
#undef GSTA
#undef GCPB
}

// ======================= CSR build ===========================================
__global__ void hist2(const int* __restrict__ l_e, const int* __restrict__ c_e,
                      int* __restrict__ cnt_l, int* __restrict__ cnt_c, int E)
{
    int i = blockIdx.x * blockDim.x + threadIdx.x;
    if (i < E) {
        atomicAdd(&cnt_l[l_e[i]], 1);
        atomicAdd(&cnt_c[c_e[i]], 1);
    }
}

__global__ void exscan(const int* __restrict__ cnt, int* __restrict__ off, int n)
{
    __shared__ int part[1024];
    const int t = threadIdx.x;
    const int chunk = (n + 1023) >> 10;
    const int b = t * chunk;
    const int e = min(b + chunk, n);
    int s = 0;
    for (int i = b; i < e; i++) s += cnt[i];
    part[t] = s;
    __syncthreads();
    for (int d = 1; d < 1024; d <<= 1) {
        int v = (t >= d) ? part[t - d] : 0;
        __syncthreads();
        if (t >= d) part[t] += v;
        __syncthreads();
    }
    int run = (t == 0) ? 0 : part[t - 1];
    for (int i = b; i < e; i++) { off[i] = run; run += cnt[i]; }
    if (t == 0) off[n] = part[1023];
}

__global__ void fill2(const int* __restrict__ l_e, const int* __restrict__ c_e,
                      int* __restrict__ cur_l, int* __restrict__ cur_c,
                      int* __restrict__ src_l, int* __restrict__ src_c, int E)
{
    int i = blockIdx.x * blockDim.x + threadIdx.x;
    if (i < E) {
        int l = l_e[i], c = c_e[i];
        src_c[atomicAdd(&cur_c[c], 1)] = l;
        src_l[atomicAdd(&cur_l[l], 1)] = c;
    }
}

// ======================= gather-sum ==========================================
__global__ __launch_bounds__(256)
void gather(const float* __restrict__ msg, const int* __restrict__ off,
            const int* __restrict__ srcs, float* __restrict__ aggr, int n)
{
    int node = blockIdx.x * 8 + (threadIdx.x >> 5);
    if (node >= n) return;
    int lane = threadIdx.x & 31;
    int b = off[node], e = off[node + 1];
    float4 acc = {0.f, 0.f, 0.f, 0.f};
    for (int i = b; i < e; i++) {
        const float4 v = *((const float4*)(msg + (size_t)srcs[i] * DIM) + lane);
        acc.x += v.x; acc.y += v.y; acc.z += v.z; acc.w += v.w;
    }
    *((float4*)(aggr + (size_t)node * DIM) + lane) = acc;
}

// ---------------- launch ------------------------------------------------------
extern "C" void kernel_launch(void* const* d_in, const int* in_sizes, int n_in,
                              void* d_out, int out_size)
{
    const int D = DIM;
    const int E = in_sizes[2];
    const int L = in_sizes[4] / D;
    const int C = in_sizes[5] / D;

    const int*   l_edge = (const int*)d_in[2];
    const int*   c_edge = (const int*)d_in[3];
    const float* l_emb0 = (const float*)d_in[4];
    const float* c_emb0 = (const float*)d_in[5];

    const float* l2c_W0 = (const float*)d_in[6];
    const float* l2c_b0 = (const float*)d_in[7];
    const float* l2c_W1 = (const float*)d_in[8];
    const float* l2c_b1 = (const float*)d_in[9];
    const float* c2l_W0 = (const float*)d_in[10];
    const float* c2l_b0 = (const float*)d_in[11];
    const float* c2l_W1 = (const float*)d_in[12];
    const float* c2l_b1 = (const float*)d_in[13];
    const float* l2l_W0 = (const float*)d_in[14];
    const float* l2l_b0 = (const float*)d_in[15];
    const float* l2l_W1 = (const float*)d_in[16];
    const float* l2l_b1 = (const float*)d_in[17];
    const float* c_Wih  = (const float*)d_in[18];
    const float* c_Whh  = (const float*)d_in[19];
    const float* c_bih  = (const float*)d_in[20];
    const float* c_bhh  = (const float*)d_in[21];
    const float* l_Wih  = (const float*)d_in[22];
    const float* l_Whh  = (const float*)d_in[23];
    const float* l_bih  = (const float*)d_in[24];
    const float* l_bhh  = (const float*)d_in[25];

    float* out   = (float*)d_out;
    float* louts = out;                                // [9, L, D]
    float* couts = out + (size_t)(NITER + 1) * L * D;  // [9, C, D]

    float *l2c_msg, *c2l_msg, *l2l_msg, *aggr_c, *aggr_l;
    cudaGetSymbolAddress((void**)&l2c_msg, g_l2c_msg);
    cudaGetSymbolAddress((void**)&c2l_msg, g_c2l_msg);
    cudaGetSymbolAddress((void**)&l2l_msg, g_l2l_msg);
    cudaGetSymbolAddress((void**)&aggr_c,  g_aggr_c);
    cudaGetSymbolAddress((void**)&aggr_l,  g_aggr_l);

    int *cnt_c, *cnt_l, *off_c, *off_l, *cur_c, *cur_l, *src_c, *src_l;
    cudaGetSymbolAddress((void**)&cnt_c, g_cnt_c);
    cudaGetSymbolAddress((void**)&cnt_l, g_cnt_l);
    cudaGetSymbolAddress((void**)&off_c, g_off_c);
    cudaGetSymbolAddress((void**)&off_l, g_off_l);
    cudaGetSymbolAddress((void**)&cur_c, g_cur_c);
    cudaGetSymbolAddress((void**)&cur_l, g_cur_l);
    cudaGetSymbolAddress((void**)&src_c, g_src_c);
    cudaGetSymbolAddress((void**)&src_l, g_src_l);

    uint32_t *whi, *wlo;
    cudaGetSymbolAddress((void**)&whi, g_whi);
    cudaGetSymbolAddress((void**)&wlo, g_wlo);

    cudaFuncSetAttribute(gru_fused, cudaFuncAttributeMaxDynamicSharedMemorySize,
                         GRU_DSMEM);

    const int o_l2c0 = 0,      o_l2c1 = 8192,  o_c2l0 = 16384, o_c2l1 = 24576;
    const int o_l2l0 = 32768,  o_l2l1 = 40960;
    const int o_cih  = 49152,  o_chh  = 73728;
    const int o_lih  = 98304,  o_lhh  = 147456;

    // ---- pre-split weights into fragment-ordered bf16 hi/lo planes ----
    split_w<<<32, 256>>>(l2c_W0, whi + o_l2c0, wlo + o_l2c0, 8192, 64);
    split_w<<<32, 256>>>(l2c_W1, whi + o_l2c1, wlo + o_l2c1, 8192, 64);
    split_w<<<32, 256>>>(c2l_W0, whi + o_c2l0, wlo + o_c2l0, 8192, 64);
    split_w<<<32, 256>>>(c2l_W1, whi + o_c2l1, wlo + o_c2l1, 8192, 64);
    split_w<<<32, 256>>>(l2l_W0, whi + o_l2l0, wlo + o_l2l0, 8192, 64);
    split_w<<<32, 256>>>(l2l_W1, whi + o_l2l1, wlo + o_l2l1, 8192, 64);
    split_w<<<96, 256>>>(c_Wih,  whi + o_cih,  wlo + o_cih,  24576, 64);
    split_w<<<96, 256>>>(c_Whh,  whi + o_chh,  wlo + o_chh,  24576, 64);
    split_w<<<192, 256>>>(l_Wih, whi + o_lih,  wlo + o_lih,  49152, 128);
    split_w<<<96, 256>>>(l_Whh,  whi + o_lhh,  wlo + o_lhh,  24576, 64);

    // ---- CSR build (edge structure static across iterations) ----
    cudaMemsetAsync(cnt_c, 0, (size_t)C * sizeof(int));
    cudaMemsetAsync(cnt_l, 0, (size_t)L * sizeof(int));
    hist2<<<(E + 255) / 256, 256>>>(l_edge, c_edge, cnt_l, cnt_c, E);
    exscan<<<1, 1024>>>(cnt_c, off_c, C);
    exscan<<<1, 1024>>>(cnt_l, off_l, L);
    cudaMemcpyAsync(cur_c, off_c, (size_t)C * sizeof(int), cudaMemcpyDeviceToDevice);
    cudaMemcpyAsync(cur_l, off_l, (size_t)L * sizeof(int), cudaMemcpyDeviceToDevice);
    fill2<<<(E + 255) / 256, 256>>>(l_edge, c_edge, cur_l, cur_c, src_l, src_c, E);

    // iteration-0 slices = inputs
    cudaMemcpyAsync(louts, l_emb0, (size_t)L * D * sizeof(float), cudaMemcpyDeviceToDevice);
    cudaMemcpyAsync(couts, c_emb0, (size_t)C * D * sizeof(float), cudaMemcpyDeviceToDevice);

    const int gLx = (L + 127) / 128;
    const int gCx = (C + 127) / 128;
    const int gLg = (L + 31) / 32;
    const int gCg = (C + 31) / 32;

    for (int it = 0; it < NITER; it++) {
        const float* l_prev = louts + (size_t)it * L * D;
        const float* c_prev = couts + (size_t)it * C * D;
        float* l_next = louts + (size_t)(it + 1) * L * D;
        float* c_next = couts + (size_t)(it + 1) * C * D;

        // message MLPs (fused 2-layer)
        mlp2_bf3<<<gLx, 256>>>(l_prev, whi + o_l2c0, wlo + o_l2c0, l2c_b0,
                               whi + o_l2c1, wlo + o_l2c1, l2c_b1, l2c_msg, L, 0);
        mlp2_bf3<<<gCx, 256>>>(c_prev, whi + o_c2l0, wlo + o_c2l0, c2l_b0,
                               whi + o_c2l1, wlo + o_c2l1, c2l_b1, c2l_msg, C, 0);
        mlp2_bf3<<<gLx, 256>>>(l_prev, whi + o_l2l0, wlo + o_l2l0, l2l_b0,
                               whi + o_l2l1, wlo + o_l2l1, l2l_b1, l2l_msg, L, 1);

        // clause side: gather + fused GRU
        gather<<<(C + 7) / 8, 256>>>(l2c_msg, off_c, src_c, aggr_c, C);
        gru_fused<<<gCg, 256, GRU_DSMEM>>>(aggr_c, nullptr, 128,
                                           whi + o_cih, wlo + o_cih, c_bih,
                                           whi + o_chh, wlo + o_chh, c_bhh,
                                           c_prev, c_next, C);

        // literal side: gather + fused GRU (gi input = concat(aggr_l, l2l_msg))
        gather<<<(L + 7) / 8, 256>>>(c2l_msg, off_l, src_l, aggr_l, L);
        gru_fused<<<gLg, 256, GRU_DSMEM>>>(aggr_l, l2l_msg, 256,
                                           whi + o_lih, wlo + o_lih, l_bih,
                                           whi + o_lhh, wlo + o_lhh, l_bhh,
                                           l_prev, l_next, L);
    }
}

// round 8
// speedup vs baseline: 1.6119x; 1.6119x over previous
#include <cuda_runtime.h>
#include <cuda_bf16.h>
#include <cstdint>

// Problem constants (fixed by setup_inputs)
#define DIM   128
#define LMAX  60000
#define CMAX  30000
#define EMAX  360000
#define NITER 8

// ---------------- scratch (device globals; no allocations allowed) ----------
__device__ float g_l2c_msg[(size_t)LMAX * DIM];
__device__ float g_c2l_msg[(size_t)CMAX * DIM];
__device__ float g_l2l_msg[(size_t)LMAX * DIM];
__device__ float g_aggr_c [(size_t)CMAX * DIM];
__device__ float g_aggr_l [(size_t)LMAX * DIM];
// CSR scratch
__device__ int g_cnt_c[CMAX];
__device__ int g_cnt_l[LMAX];
__device__ int g_off_c[CMAX + 1];
__device__ int g_off_l[LMAX + 1];
__device__ int g_cur_c[CMAX];
__device__ int g_cur_l[LMAX];
__device__ int g_src_c[EMAX];
__device__ int g_src_l[EMAX];
// pre-split bf16 weight planes (u32 = 2 bf16), fragment-ordered
#define WSPLIT_TOTAL 172032
__device__ uint32_t g_whi[WSPLIT_TOTAL];
__device__ uint32_t g_wlo[WSPLIT_TOTAL];

// ======================= helpers =============================================
__device__ __forceinline__ uint32_t smem_u32(const void* p) {
    uint32_t a;
    asm("{ .reg .u64 t; cvta.to.shared.u64 t, %1; cvt.u32.u64 %0, t; }"
        : "=r"(a) : "l"(p));
    return a;
}

__device__ __forceinline__ uint32_t pack_bf16(float lo, float hi) {
    uint32_t r;
    asm("cvt.rn.bf16x2.f32 %0, %1, %2;" : "=r"(r) : "f"(hi), "f"(lo));
    return r;
}

__device__ __forceinline__ void split2(float x, float y, uint32_t& hi, uint32_t& lo) {
    uint32_t h = pack_bf16(x, y);
    float hx = __uint_as_float(h << 16);
    float hy = __uint_as_float(h & 0xffff0000u);
    hi = h;
    lo = pack_bf16(x - hx, y - hy);
}

__device__ __forceinline__ void cp16(uint32_t dst, const void* src) {
    asm volatile("cp.async.ca.shared.global [%0], [%1], 16;"
                 :: "r"(dst), "l"(src) : "memory");
}
#define CP_COMMIT() asm volatile("cp.async.commit_group;" ::: "memory")
#define CP_WAIT0()  asm volatile("cp.async.wait_group 0;" ::: "memory")
#define CP_WAIT1()  asm volatile("cp.async.wait_group 1;" ::: "memory")

__device__ __forceinline__ void mma_bf16(float* d, const uint32_t* a,
                                         uint32_t b0, uint32_t b1) {
    asm volatile(
        "mma.sync.aligned.m16n8k16.row.col.f32.bf16.bf16.f32 "
        "{%0,%1,%2,%3}, {%4,%5,%6,%7}, {%8,%9}, {%0,%1,%2,%3};"
        : "+f"(d[0]), "+f"(d[1]), "+f"(d[2]), "+f"(d[3])
        : "r"(a[0]), "r"(a[1]), "r"(a[2]), "r"(a[3]), "r"(b0), "r"(b1));
}

#define IDX(r, q) ((((r) << 3)) | ((q) ^ ((r) & 7)))

__device__ __forceinline__ float fsigmoid(float x) { return 1.f / (1.f + __expf(-x)); }
__device__ __forceinline__ float ftanh(float x) {
    float t = __expf(2.f * fabsf(x));
    float r = 1.f - 2.f / (t + 1.f);
    return copysignf(r, x);
}

// ======================= weight pre-split (fragment-ordered) =================
__global__ void split_w(const float* __restrict__ W, uint32_t* __restrict__ hi,
                        uint32_t* __restrict__ lo, int total_pairs, int kp)
{
    int i = blockIdx.x * 256 + threadIdx.x;
    if (i >= total_pairs) return;
    int R = i / kp, p = i - R * kp;
    float2 f = ((const float2*)W)[i];
    uint32_t h, l;
    split2(f.x, f.y, h, l);
    int ngroup = R >> 7, n = R & 127;
    int ch = p >> 3, q = p & 7;
    int nt = n >> 3, l4 = n & 7;
    int region = l4 * 4 + (q & 3);
    int idx = region * 32 + (((nt >> 1) ^ (region & 7)) << 2) + ((nt & 1) << 1) + (q >> 2);
    size_t base = ((size_t)(ngroup * (kp >> 3) + ch)) << 10;
    hi[base + idx] = h;
    lo[base + idx] = l;
}

// ======================= MMA chunk (128 rows x 128 cols) =====================
// buffer layout (u32): [Ah 1024][Al 1024][Bh 1024][Bl 1024] = 16KB
__device__ __forceinline__ void mma_chunk_v(const uint32_t* __restrict__ sb,
                                            float (&acc)[16][4], int lane, int wid)
{
    const uint32_t* Ah = sb;
    const uint32_t* Al = sb + 1024;
    const int r = wid * 16 + (lane >> 2);
    const int q = lane & 3;
    uint32_t ah[4], al[4];
    ah[0] = Ah[IDX(r, q)];     ah[1] = Ah[IDX(r + 8, q)];
    ah[2] = Ah[IDX(r, q + 4)]; ah[3] = Ah[IDX(r + 8, q + 4)];
    al[0] = Al[IDX(r, q)];     al[1] = Al[IDX(r + 8, q)];
    al[2] = Al[IDX(r, q + 4)]; al[3] = Al[IDX(r + 8, q + 4)];
    const uint32_t* Bh = sb + 2048 + lane * 32;
    const uint32_t* Bl = Bh + 1024;
#pragma unroll
    for (int c = 0; c < 8; c++) {
        const int sw = ((c ^ (lane & 7)) << 2);
        uint4 vh = *(const uint4*)(Bh + sw);
        uint4 vl = *(const uint4*)(Bl + sw);
        mma_bf16(acc[2 * c],     ah, vh.x, vh.y);
        mma_bf16(acc[2 * c],     al, vh.x, vh.y);
        mma_bf16(acc[2 * c],     ah, vl.x, vl.y);
        mma_bf16(acc[2 * c + 1], ah, vh.z, vh.w);
        mma_bf16(acc[2 * c + 1], al, vh.z, vh.w);
        mma_bf16(acc[2 * c + 1], ah, vl.z, vl.w);
    }
}

__device__ __forceinline__ void mma_chunk_areg_v(const uint32_t* __restrict__ sb,
                                                 const float (&a1)[16][4], float (&acc)[16][4],
                                                 int c2, int lane)
{
    uint32_t ah[4], al[4];
    split2(a1[2 * c2][0],     a1[2 * c2][1],     ah[0], al[0]);
    split2(a1[2 * c2][2],     a1[2 * c2][3],     ah[1], al[1]);
    split2(a1[2 * c2 + 1][0], a1[2 * c2 + 1][1], ah[2], al[2]);
    split2(a1[2 * c2 + 1][2], a1[2 * c2 + 1][3], ah[3], al[3]);
    const uint32_t* Bh = sb + 2048 + lane * 32;
    const uint32_t* Bl = Bh + 1024;
#pragma unroll
    for (int c = 0; c < 8; c++) {
        const int sw = ((c ^ (lane & 7)) << 2);
        uint4 vh = *(const uint4*)(Bh + sw);
        uint4 vl = *(const uint4*)(Bl + sw);
        mma_bf16(acc[2 * c],     ah, vh.x, vh.y);
        mma_bf16(acc[2 * c],     al, vh.x, vh.y);
        mma_bf16(acc[2 * c],     ah, vl.x, vl.y);
        mma_bf16(acc[2 * c + 1], ah, vh.z, vh.w);
        mma_bf16(acc[2 * c + 1], al, vh.z, vh.w);
        mma_bf16(acc[2 * c + 1], ah, vl.z, vl.w);
    }
}

// ======================= fused 2-layer MLP (unchanged from R5) ===============
__global__ __launch_bounds__(256, 1)
void mlp2_bf3(const float* __restrict__ A0,
              const uint32_t* __restrict__ W0h, const uint32_t* __restrict__ W0l,
              const float* __restrict__ b0,
              const uint32_t* __restrict__ W1h, const uint32_t* __restrict__ W1l,
              const float* __restrict__ b1,
              float* __restrict__ out, int N, int perm)
{
    __shared__ __align__(16) uint32_t sm[3 * 4096];
    __shared__ float sb0[128];

    const int t = threadIdx.x, lane = t & 31, wid = t >> 5;
    const int m0 = blockIdx.x * 128;

    if (t < 128) sb0[t] = b0[t];

    float acc1[16][4];
#pragma unroll
    for (int i = 0; i < 16; i++)
#pragma unroll
        for (int j = 0; j < 4; j++) acc1[i][j] = 0.f;

    const int arow_l = t >> 1;
    const int afl = (t & 1) * 8;
    const int grow = m0 + arow_l;
    int arow = (perm ? (grow ^ 1) : grow);
    if (grow >= N) arow = 0;
    float4 ra0, ra1;

    const int wrow = t & 127;
    const int wpl = t >> 7;
    const uint32_t* w0p = wpl ? W0l : W0h;
    const uint32_t* w1p = wpl ? W1l : W1h;

#define LDA1(ch) do { \
        const float* p = A0 + (size_t)arow * 128 + ((ch) << 4) + afl; \
        ra0 = *(const float4*)p; ra1 = *(const float4*)(p + 4); \
    } while (0)
#define STA1(buf) do { \
        uint32_t* Ah = sm + (buf) * 4096; \
        uint32_t* Al = Ah + 1024; \
        uint32_t h0, l0; \
        split2(ra0.x, ra0.y, h0, l0); Ah[IDX(arow_l, (afl >> 1) + 0)] = h0; Al[IDX(arow_l, (afl >> 1) + 0)] = l0; \
        split2(ra0.z, ra0.w, h0, l0); Ah[IDX(arow_l, (afl >> 1) + 1)] = h0; Al[IDX(arow_l, (afl >> 1) + 1)] = l0; \
        split2(ra1.x, ra1.y, h0, l0); Ah[IDX(arow_l, (afl >> 1) + 2)] = h0; Al[IDX(arow_l, (afl >> 1) + 2)] = l0; \
        split2(ra1.z, ra1.w, h0, l0); Ah[IDX(arow_l, (afl >> 1) + 3)] = h0; Al[IDX(arow_l, (afl >> 1) + 3)] = l0; \
    } while (0)
#define CPW1(wb, ch, buf) do { \
        const uint32_t* gp = (wb) + ((size_t)(ch) << 10) + wrow * 8; \
        uint32_t daddr = smem_u32(sm + (buf) * 4096 + (2 + wpl) * 1024 + wrow * 8); \
        cp16(daddr, gp); cp16(daddr + 16, gp + 4); \
    } while (0)

    // ---- stage 1 ----
    LDA1(0); CPW1(w0p, 0, 0); CP_COMMIT(); STA1(0);
    LDA1(1); CPW1(w0p, 1, 1); CP_COMMIT(); STA1(1); CP_WAIT1();
    __syncthreads();
    for (int ch = 0; ch < 8; ch++) {
        mma_chunk_v(sm + (ch % 3) * 4096, acc1, lane, wid);
        if (ch + 1 < 8) {
            if (ch + 2 < 8) {
                LDA1(ch + 2); CPW1(w0p, ch + 2, (ch + 2) % 3); CP_COMMIT();
                STA1((ch + 2) % 3);
                CP_WAIT1();
            } else CP_WAIT0();
            __syncthreads();
        }
    }
    __syncthreads();

#pragma unroll
    for (int nt = 0; nt < 16; nt++) {
        const int col = nt * 8 + 2 * (lane & 3);
        float bx = sb0[col], by = sb0[col + 1];
        acc1[nt][0] = fmaxf(acc1[nt][0] + bx, 0.f);
        acc1[nt][1] = fmaxf(acc1[nt][1] + by, 0.f);
        acc1[nt][2] = fmaxf(acc1[nt][2] + bx, 0.f);
        acc1[nt][3] = fmaxf(acc1[nt][3] + by, 0.f);
    }

    float acc2[16][4];
#pragma unroll
    for (int i = 0; i < 16; i++)
#pragma unroll
        for (int j = 0; j < 4; j++) acc2[i][j] = 0.f;

    CPW1(w1p, 0, 0); CP_COMMIT();
    CPW1(w1p, 1, 1); CP_COMMIT(); CP_WAIT1();
    __syncthreads();
    for (int ch = 0; ch < 8; ch++) {
        mma_chunk_areg_v(sm + (ch % 3) * 4096, acc1, acc2, ch, lane);
        if (ch + 1 < 8) {
            if (ch + 2 < 8) { CPW1(w1p, ch + 2, (ch + 2) % 3); CP_COMMIT(); CP_WAIT1(); }
            else CP_WAIT0();
            __syncthreads();
        }
    }

    const int r0 = m0 + wid * 16 + (lane >> 2);
#pragma unroll
    for (int nt = 0; nt < 16; nt++) {
        const int col = nt * 8 + 2 * (lane & 3);
        float bx = b1[col], by = b1[col + 1];
        if (r0 < N)
            *(float2*)(out + (size_t)r0 * 128 + col) =
                make_float2(acc2[nt][0] + bx, acc2[nt][1] + by);
        if (r0 + 8 < N)
            *(float2*)(out + (size_t)(r0 + 8) * 128 + col) =
                make_float2(acc2[nt][2] + bx, acc2[nt][3] + by);
    }
#undef LDA1
#undef STA1
#undef CPW1
}

// ======================= fused GRU (128-row CTA, 4 K-passes) =================
// One generic GEMM pass: acc += concat(S0,S1,S2) @ Wsel^T over nch chunks.
// W chunks: first na from Wa planes, rest from Wb planes.
__device__ __forceinline__ void gru_pass(
    uint32_t* __restrict__ sm, float (&acc)[16][4],
    const float* __restrict__ S0, int n0,
    const float* __restrict__ S1, int n1,
    const float* __restrict__ S2, int n2,
    const uint32_t* __restrict__ Wa_h, const uint32_t* __restrict__ Wa_l, int na,
    const uint32_t* __restrict__ Wb_h, const uint32_t* __restrict__ Wb_l,
    int arow, int t, int lane, int wid)
{
    const int nch = n0 + n1 + n2;
    const int arow_l = t >> 1;
    const int afl = (t & 1) * 8;
    const int wrow = t & 127;
    const int wpl = t >> 7;
    float4 ra0, ra1;

    auto lda = [&](int ch) {
        const float* src; int col;
        if (ch < n0)            { src = S0; col = ch << 4; }
        else if (ch < n0 + n1)  { src = S1; col = (ch - n0) << 4; }
        else                    { src = S2; col = (ch - n0 - n1) << 4; }
        const float* p = src + (size_t)arow * 128 + col + afl;
        ra0 = *(const float4*)p; ra1 = *(const float4*)(p + 4);
    };
    auto sta = [&](int buf) {
        uint32_t* Ah = sm + buf * 4096;
        uint32_t* Al = Ah + 1024;
        uint32_t h0, l0;
        split2(ra0.x, ra0.y, h0, l0); Ah[IDX(arow_l, (afl >> 1) + 0)] = h0; Al[IDX(arow_l, (afl >> 1) + 0)] = l0;
        split2(ra0.z, ra0.w, h0, l0); Ah[IDX(arow_l, (afl >> 1) + 1)] = h0; Al[IDX(arow_l, (afl >> 1) + 1)] = l0;
        split2(ra1.x, ra1.y, h0, l0); Ah[IDX(arow_l, (afl >> 1) + 2)] = h0; Al[IDX(arow_l, (afl >> 1) + 2)] = l0;
        split2(ra1.z, ra1.w, h0, l0); Ah[IDX(arow_l, (afl >> 1) + 3)] = h0; Al[IDX(arow_l, (afl >> 1) + 3)] = l0;
    };
    auto cpw = [&](int ch, int buf) {
        const uint32_t* gp = (ch < na)
            ? (wpl ? Wa_l : Wa_h) + (((size_t)ch) << 10) + wrow * 8
            : (wpl ? Wb_l : Wb_h) + (((size_t)(ch - na)) << 10) + wrow * 8;
        uint32_t daddr = smem_u32(sm + buf * 4096 + (2 + wpl) * 1024 + wrow * 8);
        cp16(daddr, gp); cp16(daddr + 16, gp + 4);
    };

    lda(0); cpw(0, 0); CP_COMMIT(); sta(0);
    lda(1); cpw(1, 1); CP_COMMIT(); sta(1); CP_WAIT1();
    __syncthreads();
    for (int ch = 0; ch < nch; ch++) {
        mma_chunk_v(sm + (ch % 3) * 4096, acc, lane, wid);
        if (ch + 1 < nch) {
            if (ch + 2 < nch) {
                lda(ch + 2); cpw(ch + 2, (ch + 2) % 3); CP_COMMIT();
                sta((ch + 2) % 3);
                CP_WAIT1();
            } else CP_WAIT0();
            __syncthreads();
        }
    }
    __syncthreads();   // protect buffers before next pass's prologue
}

#define ZERO_ACC(a) do { \
    _Pragma("unroll") for (int _i = 0; _i < 16; _i++) \
    _Pragma("unroll") for (int _j = 0; _j < 4; _j++) (a)[_i][_j] = 0.f; } while (0)

// gate order in weights: rows [0:128)=r, [128:256)=z, [256:384)=n
__global__ __launch_bounds__(256, 1)
void gru_fused2(const float* __restrict__ giA0, const float* __restrict__ giA1,
                int n0, int n1,
                const uint32_t* __restrict__ Wih_h, const uint32_t* __restrict__ Wih_l,
                const float* __restrict__ bih,
                const uint32_t* __restrict__ Whh_h, const uint32_t* __restrict__ Whh_l,
                const float* __restrict__ bhh,
                const float* __restrict__ hprev, float* __restrict__ hnext, int N)
{
    __shared__ __align__(16) uint32_t sm[3 * 4096];
    __shared__ float sbi[384], sbh[384];

    const int t = threadIdx.x, lane = t & 31, wid = t >> 5;
    const int m0 = blockIdx.x * 128;
    for (int i = t; i < 384; i += 256) { sbi[i] = bih[i]; sbh[i] = bhh[i]; }
    __syncthreads();

    int arow = m0 + (t >> 1);
    if (arow >= N) arow = 0;

    const int nchi = n0 + n1;          // gi K chunks
    const size_t CHW = 1024;           // u32 per chunk plane

    float accA[16][4], accB[16][4];

    // ---- pass 1: hn = h @ Whh_n^T -> accA ----
    // Wa = Whh gate-n planes (chunks 16..23 of Whh); all 8 chunks from Wa.
    ZERO_ACC(accA);
    gru_pass(sm, accA, hprev, 8, nullptr, 0, nullptr, 0,
             Whh_h + 2 * 8 * CHW, Whh_l + 2 * 8 * CHW, 8,
             Whh_h, Whh_l,
             arow, t, lane, wid);

    // ---- pass 2: r_acc = [gi, h] @ W_r^T -> accB ----
    ZERO_ACC(accB);
    gru_pass(sm, accB, giA0, n0, giA1, n1, hprev, 8,
             Wih_h, Wih_l, nchi,
             Whh_h, Whh_l,
             arow, t, lane, wid);

    // fold: accA = sigmoid(r) * (hn + bhn)
#pragma unroll
    for (int nt = 0; nt < 16; nt++) {
        const int jc = nt * 8 + 2 * (lane & 3);
        float br0 = sbi[jc] + sbh[jc], br1 = sbi[jc + 1] + sbh[jc + 1];
        float bh0 = sbh[256 + jc], bh1 = sbh[256 + jc + 1];
        accA[nt][0] = fsigmoid(accB[nt][0] + br0) * (accA[nt][0] + bh0);
        accA[nt][1] = fsigmoid(accB[nt][1] + br1) * (accA[nt][1] + bh1);
        accA[nt][2] = fsigmoid(accB[nt][2] + br0) * (accA[nt][2] + bh0);
        accA[nt][3] = fsigmoid(accB[nt][3] + br1) * (accA[nt][3] + bh1);
    }

    // ---- pass 3: in_acc = gi @ Wih_n^T -> accB; accA = tanh(in + bin + accA) ----
    ZERO_ACC(accB);
    gru_pass(sm, accB, giA0, n0, giA1, n1, nullptr, 0,
             Wih_h + 2 * (size_t)nchi * CHW, Wih_l + 2 * (size_t)nchi * CHW, nchi,
             Whh_h, Whh_l,
             arow, t, lane, wid);
#pragma unroll
    for (int nt = 0; nt < 16; nt++) {
        const int jc = nt * 8 + 2 * (lane & 3);
        float bi0 = sbi[256 + jc], bi1 = sbi[256 + jc + 1];
        accA[nt][0] = ftanh(accB[nt][0] + bi0 + accA[nt][0]);
        accA[nt][1] = ftanh(accB[nt][1] + bi1 + accA[nt][1]);
        accA[nt][2] = ftanh(accB[nt][2] + bi0 + accA[nt][2]);
        accA[nt][3] = ftanh(accB[nt][3] + bi1 + accA[nt][3]);
    }

    // ---- pass 4: z_acc = [gi, h] @ W_z^T -> accB; write h_next ----
    ZERO_ACC(accB);
    gru_pass(sm, accB, giA0, n0, giA1, n1, hprev, 8,
             Wih_h + (size_t)nchi * CHW, Wih_l + (size_t)nchi * CHW, nchi,
             Whh_h + 8 * CHW, Whh_l + 8 * CHW,
             arow, t, lane, wid);

    const int r0 = m0 + wid * 16 + (lane >> 2);
#pragma unroll
    for (int nt = 0; nt < 16; nt++) {
        const int jc = nt * 8 + 2 * (lane & 3);
        float bz0 = sbi[128 + jc] + sbh[128 + jc];
        float bz1 = sbi[128 + jc + 1] + sbh[128 + jc + 1];
        if (r0 < N) {
            float2 h2 = *(const float2*)(hprev + (size_t)r0 * 128 + jc);
            float z0 = fsigmoid(accB[nt][0] + bz0);
            float z1 = fsigmoid(accB[nt][1] + bz1);
            float2 o;
            o.x = (1.f - z0) * accA[nt][0] + z0 * h2.x;
            o.y = (1.f - z1) * accA[nt][1] + z1 * h2.y;
            *(float2*)(hnext + (size_t)r0 * 128 + jc) = o;
        }
        if (r0 + 8 < N) {
            float2 h2 = *(const float2*)(hprev + (size_t)(r0 + 8) * 128 + jc);
            float z0 = fsigmoid(accB[nt][2] + bz0);
            float z1 = fsigmoid(accB[nt][3] + bz1);
            float2 o;
            o.x = (1.f - z0) * accA[nt][2] + z0 * h2.x;
            o.y = (1.f - z1) * accA[nt][3] + z1 * h2.y;
            *(float2*)(hnext + (size_t)(r0 + 8) * 128 + jc) = o;
        }
    }
}

// ======================= CSR build ===========================================
__global__ void hist2(const int* __restrict__ l_e, const int* __restrict__ c_e,
                      int* __restrict__ cnt_l, int* __restrict__ cnt_c, int E)
{
    int i = blockIdx.x * blockDim.x + threadIdx.x;
    if (i < E) {
        atomicAdd(&cnt_l[l_e[i]], 1);
        atomicAdd(&cnt_c[c_e[i]], 1);
    }
}

__global__ void exscan(const int* __restrict__ cnt, int* __restrict__ off, int n)
{
    __shared__ int part[1024];
    const int t = threadIdx.x;
    const int chunk = (n + 1023) >> 10;
    const int b = t * chunk;
    const int e = min(b + chunk, n);
    int s = 0;
    for (int i = b; i < e; i++) s += cnt[i];
    part[t] = s;
    __syncthreads();
    for (int d = 1; d < 1024; d <<= 1) {
        int v = (t >= d) ? part[t - d] : 0;
        __syncthreads();
        if (t >= d) part[t] += v;
        __syncthreads();
    }
    int run = (t == 0) ? 0 : part[t - 1];
    for (int i = b; i < e; i++) { off[i] = run; run += cnt[i]; }
    if (t == 0) off[n] = part[1023];
}

__global__ void fill2(const int* __restrict__ l_e, const int* __restrict__ c_e,
                      int* __restrict__ cur_l, int* __restrict__ cur_c,
                      int* __restrict__ src_l, int* __restrict__ src_c, int E)
{
    int i = blockIdx.x * blockDim.x + threadIdx.x;
    if (i < E) {
        int l = l_e[i], c = c_e[i];
        src_c[atomicAdd(&cur_c[c], 1)] = l;
        src_l[atomicAdd(&cur_l[l], 1)] = c;
    }
}

// ======================= gather-sum ==========================================
__global__ __launch_bounds__(256)
void gather(const float* __restrict__ msg, const int* __restrict__ off,
            const int* __restrict__ srcs, float* __restrict__ aggr, int n)
{
    int node = blockIdx.x * 8 + (threadIdx.x >> 5);
    if (node >= n) return;
    int lane = threadIdx.x & 31;
    int b = off[node], e = off[node + 1];
    float4 acc = {0.f, 0.f, 0.f, 0.f};
    for (int i = b; i < e; i++) {
        const float4 v = *((const float4*)(msg + (size_t)srcs[i] * DIM) + lane);
        acc.x += v.x; acc.y += v.y; acc.z += v.z; acc.w += v.w;
    }
    *((float4*)(aggr + (size_t)node * DIM) + lane) = acc;
}

// ---------------- launch ------------------------------------------------------
extern "C" void kernel_launch(void* const* d_in, const int* in_sizes, int n_in,
                              void* d_out, int out_size)
{
    const int D = DIM;
    const int E = in_sizes[2];
    const int L = in_sizes[4] / D;
    const int C = in_sizes[5] / D;

    const int*   l_edge = (const int*)d_in[2];
    const int*   c_edge = (const int*)d_in[3];
    const float* l_emb0 = (const float*)d_in[4];
    const float* c_emb0 = (const float*)d_in[5];

    const float* l2c_W0 = (const float*)d_in[6];
    const float* l2c_b0 = (const float*)d_in[7];
    const float* l2c_W1 = (const float*)d_in[8];
    const float* l2c_b1 = (const float*)d_in[9];
    const float* c2l_W0 = (const float*)d_in[10];
    const float* c2l_b0 = (const float*)d_in[11];
    const float* c2l_W1 = (const float*)d_in[12];
    const float* c2l_b1 = (const float*)d_in[13];
    const float* l2l_W0 = (const float*)d_in[14];
    const float* l2l_b0 = (const float*)d_in[15];
    const float* l2l_W1 = (const float*)d_in[16];
    const float* l2l_b1 = (const float*)d_in[17];
    const float* c_Wih  = (const float*)d_in[18];
    const float* c_Whh  = (const float*)d_in[19];
    const float* c_bih  = (const float*)d_in[20];
    const float* c_bhh  = (const float*)d_in[21];
    const float* l_Wih  = (const float*)d_in[22];
    const float* l_Whh  = (const float*)d_in[23];
    const float* l_bih  = (const float*)d_in[24];
    const float* l_bhh  = (const float*)d_in[25];

    float* out   = (float*)d_out;
    float* louts = out;                                // [9, L, D]
    float* couts = out + (size_t)(NITER + 1) * L * D;  // [9, C, D]

    float *l2c_msg, *c2l_msg, *l2l_msg, *aggr_c, *aggr_l;
    cudaGetSymbolAddress((void**)&l2c_msg, g_l2c_msg);
    cudaGetSymbolAddress((void**)&c2l_msg, g_c2l_msg);
    cudaGetSymbolAddress((void**)&l2l_msg, g_l2l_msg);
    cudaGetSymbolAddress((void**)&aggr_c,  g_aggr_c);
    cudaGetSymbolAddress((void**)&aggr_l,  g_aggr_l);

    int *cnt_c, *cnt_l, *off_c, *off_l, *cur_c, *cur_l, *src_c, *src_l;
    cudaGetSymbolAddress((void**)&cnt_c, g_cnt_c);
    cudaGetSymbolAddress((void**)&cnt_l, g_cnt_l);
    cudaGetSymbolAddress((void**)&off_c, g_off_c);
    cudaGetSymbolAddress((void**)&off_l, g_off_l);
    cudaGetSymbolAddress((void**)&cur_c, g_cur_c);
    cudaGetSymbolAddress((void**)&cur_l, g_cur_l);
    cudaGetSymbolAddress((void**)&src_c, g_src_c);
    cudaGetSymbolAddress((void**)&src_l, g_src_l);

    uint32_t *whi, *wlo;
    cudaGetSymbolAddress((void**)&whi, g_whi);
    cudaGetSymbolAddress((void**)&wlo, g_wlo);

    const int o_l2c0 = 0,      o_l2c1 = 8192,  o_c2l0 = 16384, o_c2l1 = 24576;
    const int o_l2l0 = 32768,  o_l2l1 = 40960;
    const int o_cih  = 49152,  o_chh  = 73728;
    const int o_lih  = 98304,  o_lhh  = 147456;

    // ---- pre-split weights into fragment-ordered bf16 hi/lo planes ----
    split_w<<<32, 256>>>(l2c_W0, whi + o_l2c0, wlo + o_l2c0, 8192, 64);
    split_w<<<32, 256>>>(l2c_W1, whi + o_l2c1, wlo + o_l2c1, 8192, 64);
    split_w<<<32, 256>>>(c2l_W0, whi + o_c2l0, wlo + o_c2l0, 8192, 64);
    split_w<<<32, 256>>>(c2l_W1, whi + o_c2l1, wlo + o_c2l1, 8192, 64);
    split_w<<<32, 256>>>(l2l_W0, whi + o_l2l0, wlo + o_l2l0, 8192, 64);
    split_w<<<32, 256>>>(l2l_W1, whi + o_l2l1, wlo + o_l2l1, 8192, 64);
    split_w<<<96, 256>>>(c_Wih,  whi + o_cih,  wlo + o_cih,  24576, 64);
    split_w<<<96, 256>>>(c_Whh,  whi + o_chh,  wlo + o_chh,  24576, 64);
    split_w<<<192, 256>>>(l_Wih, whi + o_lih,  wlo + o_lih,  49152, 128);
    split_w<<<96, 256>>>(l_Whh,  whi + o_lhh,  wlo + o_lhh,  24576, 64);

    // ---- CSR build (edge structure static across iterations) ----
    cudaMemsetAsync(cnt_c, 0, (size_t)C * sizeof(int));
    cudaMemsetAsync(cnt_l, 0, (size_t)L * sizeof(int));
    hist2<<<(E + 255) / 256, 256>>>(l_edge, c_edge, cnt_l, cnt_c, E);
    exscan<<<1, 1024>>>(cnt_c, off_c, C);
    exscan<<<1, 1024>>>(cnt_l, off_l, L);
    cudaMemcpyAsync(cur_c, off_c, (size_t)C * sizeof(int), cudaMemcpyDeviceToDevice);
    cudaMemcpyAsync(cur_l, off_l, (size_t)L * sizeof(int), cudaMemcpyDeviceToDevice);
    fill2<<<(E + 255) / 256, 256>>>(l_edge, c_edge, cur_l, cur_c, src_l, src_c, E);

    // iteration-0 slices = inputs
    cudaMemcpyAsync(louts, l_emb0, (size_t)L * D * sizeof(float), cudaMemcpyDeviceToDevice);
    cudaMemcpyAsync(couts, c_emb0, (size_t)C * D * sizeof(float), cudaMemcpyDeviceToDevice);

    const int gLx = (L + 127) / 128;
    const int gCx = (C + 127) / 128;

    for (int it = 0; it < NITER; it++) {
        const float* l_prev = louts + (size_t)it * L * D;
        const float* c_prev = couts + (size_t)it * C * D;
        float* l_next = louts + (size_t)(it + 1) * L * D;
        float* c_next = couts + (size_t)(it + 1) * C * D;

        // message MLPs (fused 2-layer)
        mlp2_bf3<<<gLx, 256>>>(l_prev, whi + o_l2c0, wlo + o_l2c0, l2c_b0,
                               whi + o_l2c1, wlo + o_l2c1, l2c_b1, l2c_msg, L, 0);
        mlp2_bf3<<<gCx, 256>>>(c_prev, whi + o_c2l0, wlo + o_c2l0, c2l_b0,
                               whi + o_c2l1, wlo + o_c2l1, c2l_b1, c2l_msg, C, 0);
        mlp2_bf3<<<gLx, 256>>>(l_prev, whi + o_l2l0, wlo + o_l2l0, l2l_b0,
                               whi + o_l2l1, wlo + o_l2l1, l2l_b1, l2l_msg, L, 1);

        // clause side: gather + fused GRU (gi K = 128 -> n0=8, n1=0)
        gather<<<(C + 7) / 8, 256>>>(l2c_msg, off_c, src_c, aggr_c, C);
        gru_fused2<<<gCx, 256>>>(aggr_c, nullptr, 8, 0,
                                 whi + o_cih, wlo + o_cih, c_bih,
                                 whi + o_chh, wlo + o_chh, c_bhh,
                                 c_prev, c_next, C);

        // literal side: gather + fused GRU (gi = concat(aggr_l, l2l_msg), n0=n1=8)
        gather<<<(L + 7) / 8, 256>>>(c2l_msg, off_l, src_l, aggr_l, L);
        gru_fused2<<<gLx, 256>>>(aggr_l, l2l_msg, 8, 8,
                                 whi + o_lih, wlo + o_lih, l_bih,
                                 whi + o_lhh, wlo + o_lhh, l_bhh,
                                 l_prev, l_next, L);
    }
}

// round 9
// speedup vs baseline: 1.9942x; 1.2372x over previous
#include <cuda_runtime.h>
#include <cuda_bf16.h>
#include <cstdint>

// Problem constants (fixed by setup_inputs)
#define DIM   128
#define LMAX  60000
#define CMAX  30000
#define EMAX  360000
#define NITER 8

// ---------------- scratch (device globals; no allocations allowed) ----------
__device__ float g_l2c_msg[(size_t)LMAX * DIM];
__device__ float g_c2l_msg[(size_t)CMAX * DIM];
__device__ float g_l2l_msg[(size_t)LMAX * DIM];
__device__ float g_aggr_c [(size_t)CMAX * DIM];
__device__ float g_aggr_l [(size_t)LMAX * DIM];
__device__ float g_gi_c   [(size_t)CMAX * 3 * DIM];
__device__ float g_gh_c   [(size_t)CMAX * 3 * DIM];
__device__ float g_gi_l   [(size_t)LMAX * 3 * DIM];
__device__ float g_gh_l   [(size_t)LMAX * 3 * DIM];
// CSR scratch
__device__ int g_cnt_c[CMAX];
__device__ int g_cnt_l[LMAX];
__device__ int g_off_c[CMAX + 1];
__device__ int g_off_l[LMAX + 1];
__device__ int g_cur_c[CMAX];
__device__ int g_cur_l[LMAX];
__device__ int g_src_c[EMAX];
__device__ int g_src_l[EMAX];
// pre-split bf16 weight planes (u32 = 2 bf16), fragment-ordered
#define WSPLIT_TOTAL 172032
__device__ uint32_t g_whi[WSPLIT_TOTAL];
__device__ uint32_t g_wlo[WSPLIT_TOTAL];

// ======================= helpers =============================================
__device__ __forceinline__ uint32_t smem_u32(const void* p) {
    uint32_t a;
    asm("{ .reg .u64 t; cvta.to.shared.u64 t, %1; cvt.u32.u64 %0, t; }"
        : "=r"(a) : "l"(p));
    return a;
}

__device__ __forceinline__ uint32_t pack_bf16(float lo, float hi) {
    uint32_t r;
    asm("cvt.rn.bf16x2.f32 %0, %1, %2;" : "=r"(r) : "f"(hi), "f"(lo));
    return r;
}

__device__ __forceinline__ void split2(float x, float y, uint32_t& hi, uint32_t& lo) {
    uint32_t h = pack_bf16(x, y);
    float hx = __uint_as_float(h << 16);
    float hy = __uint_as_float(h & 0xffff0000u);
    hi = h;
    lo = pack_bf16(x - hx, y - hy);
}

__device__ __forceinline__ void cp16(uint32_t dst, const void* src) {
    asm volatile("cp.async.ca.shared.global [%0], [%1], 16;"
                 :: "r"(dst), "l"(src) : "memory");
}
#define CP_COMMIT() asm volatile("cp.async.commit_group;" ::: "memory")
#define CP_WAIT0()  asm volatile("cp.async.wait_group 0;" ::: "memory")
#define CP_WAIT1()  asm volatile("cp.async.wait_group 1;" ::: "memory")

__device__ __forceinline__ void mma_bf16(float* d, const uint32_t* a,
                                         uint32_t b0, uint32_t b1) {
    asm volatile(
        "mma.sync.aligned.m16n8k16.row.col.f32.bf16.bf16.f32 "
        "{%0,%1,%2,%3}, {%4,%5,%6,%7}, {%8,%9}, {%0,%1,%2,%3};"
        : "+f"(d[0]), "+f"(d[1]), "+f"(d[2]), "+f"(d[3])
        : "r"(a[0]), "r"(a[1]), "r"(a[2]), "r"(a[3]), "r"(b0), "r"(b1));
}

#define IDX(r, q) ((((r) << 3)) | ((q) ^ ((r) & 7)))

__device__ __forceinline__ float fsigmoid(float x) { return 1.f / (1.f + __expf(-x)); }
__device__ __forceinline__ float ftanh(float x) {
    float t = __expf(2.f * fabsf(x));
    float r = 1.f - 2.f / (t + 1.f);
    return copysignf(r, x);
}

// ======================= weight pre-split (fragment-ordered) =================
__global__ void split_w(const float* __restrict__ W, uint32_t* __restrict__ hi,
                        uint32_t* __restrict__ lo, int total_pairs, int kp)
{
    int i = blockIdx.x * 256 + threadIdx.x;
    if (i >= total_pairs) return;
    int R = i / kp, p = i - R * kp;
    float2 f = ((const float2*)W)[i];
    uint32_t h, l;
    split2(f.x, f.y, h, l);
    int ngroup = R >> 7, n = R & 127;
    int ch = p >> 3, q = p & 7;
    int nt = n >> 3, l4 = n & 7;
    int region = l4 * 4 + (q & 3);
    int idx = region * 32 + (((nt >> 1) ^ (region & 7)) << 2) + ((nt & 1) << 1) + (q >> 2);
    size_t base = ((size_t)(ngroup * (kp >> 3) + ch)) << 10;
    hi[base + idx] = h;
    lo[base + idx] = l;
}

// ======================= MMA chunk ===========================================
// A: [Ah 1024][Al 1024] at A; B: [Bh 1024][Bl 1024] at B.
// Interleaved accumulator chains (RAW distance 2).
__device__ __forceinline__ void mma_chunk(const uint32_t* __restrict__ A,
                                          const uint32_t* __restrict__ B,
                                          float (&acc)[16][4], int lane, int wid)
{
    const uint32_t* Ah = A;
    const uint32_t* Al = A + 1024;
    const int r = wid * 16 + (lane >> 2);
    const int q = lane & 3;
    uint32_t ah[4], al[4];
    ah[0] = Ah[IDX(r, q)];     ah[1] = Ah[IDX(r + 8, q)];
    ah[2] = Ah[IDX(r, q + 4)]; ah[3] = Ah[IDX(r + 8, q + 4)];
    al[0] = Al[IDX(r, q)];     al[1] = Al[IDX(r + 8, q)];
    al[2] = Al[IDX(r, q + 4)]; al[3] = Al[IDX(r + 8, q + 4)];
    const uint32_t* Bh = B + lane * 32;
    const uint32_t* Bl = Bh + 1024;
#pragma unroll
    for (int c = 0; c < 8; c++) {
        const int sw = ((c ^ (lane & 7)) << 2);
        uint4 vh = *(const uint4*)(Bh + sw);
        uint4 vl = *(const uint4*)(Bl + sw);
        mma_bf16(acc[2 * c],     ah, vh.x, vh.y);
        mma_bf16(acc[2 * c + 1], ah, vh.z, vh.w);
        mma_bf16(acc[2 * c],     al, vh.x, vh.y);
        mma_bf16(acc[2 * c + 1], al, vh.z, vh.w);
        mma_bf16(acc[2 * c],     ah, vl.x, vl.y);
        mma_bf16(acc[2 * c + 1], ah, vl.z, vl.w);
    }
}

// ======================= fused 2-layer MLP (occ 2) ===========================
// dyn smem layout (u32):
//   stage 1: 3 chunk buffers at buf*4096: [Ah|Al|Bh|Bl] (48KB)
//   stage 2: A region sm[0 .. 16384): chunk ch at ch*2048 ([Ah 1024][Al 1024])
//            B ring   sm[16384 .. 22528): 3 x 2048 ([Bh 1024][Bl 1024])
#define MLP2_DSMEM (22528 * 4)

__global__ __launch_bounds__(256, 2)
void mlp2_bf3(const float* __restrict__ A0,
              const uint32_t* __restrict__ W0h, const uint32_t* __restrict__ W0l,
              const float* __restrict__ b0,
              const uint32_t* __restrict__ W1h, const uint32_t* __restrict__ W1l,
              const float* __restrict__ b1,
              float* __restrict__ out, int N, int perm)
{
    extern __shared__ __align__(16) uint32_t sm[];
    __shared__ float sb0[128];

    const int t = threadIdx.x, lane = t & 31, wid = t >> 5;
    const int m0 = blockIdx.x * 128;

    if (t < 128) sb0[t] = b0[t];

    float acc1[16][4];
#pragma unroll
    for (int i = 0; i < 16; i++)
#pragma unroll
        for (int j = 0; j < 4; j++) acc1[i][j] = 0.f;

    const int arow_l = t >> 1;
    const int afl = (t & 1) * 8;
    const int grow = m0 + arow_l;
    int arow = (perm ? (grow ^ 1) : grow);
    if (grow >= N) arow = 0;
    float4 ra0, ra1;

    const int wrow = t & 127;
    const int wpl = t >> 7;
    const uint32_t* w0p = wpl ? W0l : W0h;
    const uint32_t* w1p = wpl ? W1l : W1h;

#define LDA1(ch) do { \
        const float* p = A0 + (size_t)arow * 128 + ((ch) << 4) + afl; \
        ra0 = *(const float4*)p; ra1 = *(const float4*)(p + 4); \
    } while (0)
#define STA1(buf) do { \
        uint32_t* Ah = sm + (buf) * 4096; \
        uint32_t* Al = Ah + 1024; \
        uint32_t h0, l0; \
        split2(ra0.x, ra0.y, h0, l0); Ah[IDX(arow_l, (afl >> 1) + 0)] = h0; Al[IDX(arow_l, (afl >> 1) + 0)] = l0; \
        split2(ra0.z, ra0.w, h0, l0); Ah[IDX(arow_l, (afl >> 1) + 1)] = h0; Al[IDX(arow_l, (afl >> 1) + 1)] = l0; \
        split2(ra1.x, ra1.y, h0, l0); Ah[IDX(arow_l, (afl >> 1) + 2)] = h0; Al[IDX(arow_l, (afl >> 1) + 2)] = l0; \
        split2(ra1.z, ra1.w, h0, l0); Ah[IDX(arow_l, (afl >> 1) + 3)] = h0; Al[IDX(arow_l, (afl >> 1) + 3)] = l0; \
    } while (0)
#define CPW1(wb, ch, buf) do { \
        const uint32_t* gp = (wb) + ((size_t)(ch) << 10) + wrow * 8; \
        uint32_t daddr = smem_u32(sm + (buf) * 4096 + (2 + wpl) * 1024 + wrow * 8); \
        cp16(daddr, gp); cp16(daddr + 16, gp + 4); \
    } while (0)
#define CPW2(ch, buf) do { \
        const uint32_t* gp = w1p + ((size_t)(ch) << 10) + wrow * 8; \
        uint32_t daddr = smem_u32(sm + 16384 + (buf) * 2048 + wpl * 1024 + wrow * 8); \
        cp16(daddr, gp); cp16(daddr + 16, gp + 4); \
    } while (0)

    // ---- stage 1 ----
    LDA1(0); CPW1(w0p, 0, 0); CP_COMMIT(); STA1(0);
    LDA1(1); CPW1(w0p, 1, 1); CP_COMMIT(); STA1(1); CP_WAIT1();
    __syncthreads();
    for (int ch = 0; ch < 8; ch++) {
        const uint32_t* sb = sm + (ch % 3) * 4096;
        mma_chunk(sb, sb + 2048, acc1, lane, wid);
        if (ch + 1 < 8) {
            if (ch + 2 < 8) {
                LDA1(ch + 2); CPW1(w0p, ch + 2, (ch + 2) % 3); CP_COMMIT();
                STA1((ch + 2) % 3);
                CP_WAIT1();
            } else CP_WAIT0();
            __syncthreads();
        }
    }
    __syncthreads();   // all warps done reading stage-1 buffers

    // ---- bias + relu, then spill stage-1 result into A region (pre-split) ----
    {
        const int rlo = wid * 16 + (lane >> 2);
        const int rhi = rlo + 8;
#pragma unroll
        for (int nt = 0; nt < 16; nt++) {
            const int col = nt * 8 + 2 * (lane & 3);
            float bx = sb0[col], by = sb0[col + 1];
            float v0 = fmaxf(acc1[nt][0] + bx, 0.f);
            float v1 = fmaxf(acc1[nt][1] + by, 0.f);
            float v2 = fmaxf(acc1[nt][2] + bx, 0.f);
            float v3 = fmaxf(acc1[nt][3] + by, 0.f);
            const int ch = nt >> 1;
            const int q = (nt & 1) * 4 + (lane & 3);
            uint32_t h, l;
            split2(v0, v1, h, l);
            sm[ch * 2048 + IDX(rlo, q)] = h;
            sm[ch * 2048 + 1024 + IDX(rlo, q)] = l;
            split2(v2, v3, h, l);
            sm[ch * 2048 + IDX(rhi, q)] = h;
            sm[ch * 2048 + 1024 + IDX(rhi, q)] = l;
        }
    }
    __syncthreads();

    float acc2[16][4];
#pragma unroll
    for (int i = 0; i < 16; i++)
#pragma unroll
        for (int j = 0; j < 4; j++) acc2[i][j] = 0.f;

    // ---- stage 2: A from smem region, W1 streamed into B ring ----
    CPW2(0, 0); CP_COMMIT();
    CPW2(1, 1); CP_COMMIT(); CP_WAIT1();
    __syncthreads();
    for (int ch = 0; ch < 8; ch++) {
        mma_chunk(sm + ch * 2048, sm + 16384 + (ch % 3) * 2048, acc2, lane, wid);
        if (ch + 1 < 8) {
            if (ch + 2 < 8) { CPW2(ch + 2, (ch + 2) % 3); CP_COMMIT(); CP_WAIT1(); }
            else CP_WAIT0();
            __syncthreads();
        }
    }

    const int r0 = m0 + wid * 16 + (lane >> 2);
#pragma unroll
    for (int nt = 0; nt < 16; nt++) {
        const int col = nt * 8 + 2 * (lane & 3);
        float bx = b1[col], by = b1[col + 1];
        if (r0 < N)
            *(float2*)(out + (size_t)r0 * 128 + col) =
                make_float2(acc2[nt][0] + bx, acc2[nt][1] + by);
        if (r0 + 8 < N)
            *(float2*)(out + (size_t)(r0 + 8) * 128 + col) =
                make_float2(acc2[nt][2] + bx, acc2[nt][3] + by);
    }
#undef LDA1
#undef STA1
#undef CPW1
#undef CPW2
}

// ======================= generic GEMM (R5 champion + interleave) =============
// out[N, NOtot] (cols n0..n0+127, n0 = blockIdx.y*128) = act(A @ W^T + bias)
__global__ __launch_bounds__(256, 2)
void gemm_bf3(const float* __restrict__ A0, const float* __restrict__ A1,
              const uint32_t* __restrict__ Wh, const uint32_t* __restrict__ Wl,
              const float* __restrict__ bias, float* __restrict__ out,
              int N, int NOtot, int Ktot, int relu, int perm)
{
    __shared__ __align__(16) uint32_t sm[3 * 4096];   // 48 KB, triple-buffered

    const int t = threadIdx.x, lane = t & 31, wid = t >> 5;
    const int m0 = blockIdx.x * 128;
    const int nch = Ktot >> 4;

    float acc[16][4];
#pragma unroll
    for (int i = 0; i < 16; i++)
#pragma unroll
        for (int j = 0; j < 4; j++) acc[i][j] = 0.f;

    const int arow_l = t >> 1;
    const int afl = (t & 1) * 8;
    const int grow = m0 + arow_l;
    int arow = (perm ? (grow ^ 1) : grow);
    if (grow >= N) arow = 0;
    float4 ra0, ra1;

    const int wrow = t & 127;
    const int wpl = t >> 7;
    const uint32_t* wplane = wpl ? Wl : Wh;
    const size_t wgrp = (size_t)blockIdx.y * nch;

#define LDA(ch) do { \
        const int kc = (ch) << 4; \
        const float* src = (kc < 128) ? A0 : A1; \
        const float* p = src + (size_t)arow * 128 + (kc & 127) + afl; \
        ra0 = *(const float4*)p; ra1 = *(const float4*)(p + 4); \
    } while (0)

#define STA(buf) do { \
        uint32_t* Ah = sm + (buf) * 4096; \
        uint32_t* Al = Ah + 1024; \
        uint32_t h0, l0; \
        split2(ra0.x, ra0.y, h0, l0); Ah[IDX(arow_l, (afl >> 1) + 0)] = h0; Al[IDX(arow_l, (afl >> 1) + 0)] = l0; \
        split2(ra0.z, ra0.w, h0, l0); Ah[IDX(arow_l, (afl >> 1) + 1)] = h0; Al[IDX(arow_l, (afl >> 1) + 1)] = l0; \
        split2(ra1.x, ra1.y, h0, l0); Ah[IDX(arow_l, (afl >> 1) + 2)] = h0; Al[IDX(arow_l, (afl >> 1) + 2)] = l0; \
        split2(ra1.z, ra1.w, h0, l0); Ah[IDX(arow_l, (afl >> 1) + 3)] = h0; Al[IDX(arow_l, (afl >> 1) + 3)] = l0; \
    } while (0)

#define CPW(ch, buf) do { \
        const uint32_t* gp = wplane + ((wgrp + (ch)) << 10) + wrow * 8; \
        uint32_t daddr = smem_u32(sm + (buf) * 4096 + (2 + wpl) * 1024 + wrow * 8); \
        cp16(daddr, gp); cp16(daddr + 16, gp + 4); \
    } while (0)

    LDA(0); CPW(0, 0); CP_COMMIT(); STA(0);
    if (nch > 1) { LDA(1); CPW(1, 1); CP_COMMIT(); STA(1); CP_WAIT1(); }
    else CP_WAIT0();
    __syncthreads();

    for (int ch = 0; ch < nch; ch++) {
        const uint32_t* sb = sm + (ch % 3) * 4096;
        mma_chunk(sb, sb + 2048, acc, lane, wid);
        if (ch + 1 < nch) {
            if (ch + 2 < nch) {
                LDA(ch + 2); CPW(ch + 2, (ch + 2) % 3); CP_COMMIT();
                STA((ch + 2) % 3);
                CP_WAIT1();
            } else CP_WAIT0();
            __syncthreads();
        }
    }

    const int n0 = blockIdx.y * 128;
    const int r0 = m0 + wid * 16 + (lane >> 2);
#pragma unroll
    for (int nt = 0; nt < 16; nt++) {
        const int col = n0 + nt * 8 + 2 * (lane & 3);
        float bx = bias[col], by = bias[col + 1];
        if (r0 < N) {
            float2 o = {acc[nt][0] + bx, acc[nt][1] + by};
            if (relu) { o.x = fmaxf(o.x, 0.f); o.y = fmaxf(o.y, 0.f); }
            *(float2*)(out + (size_t)r0 * NOtot + col) = o;
        }
        if (r0 + 8 < N) {
            float2 o = {acc[nt][2] + bx, acc[nt][3] + by};
            if (relu) { o.x = fmaxf(o.x, 0.f); o.y = fmaxf(o.y, 0.f); }
            *(float2*)(out + (size_t)(r0 + 8) * NOtot + col) = o;
        }
    }
#undef LDA
#undef STA
#undef CPW
}

// ======================= CSR build ===========================================
__global__ void hist2(const int* __restrict__ l_e, const int* __restrict__ c_e,
                      int* __restrict__ cnt_l, int* __restrict__ cnt_c, int E)
{
    int i = blockIdx.x * blockDim.x + threadIdx.x;
    if (i < E) {
        atomicAdd(&cnt_l[l_e[i]], 1);
        atomicAdd(&cnt_c[c_e[i]], 1);
    }
}

__global__ void exscan(const int* __restrict__ cnt, int* __restrict__ off, int n)
{
    __shared__ int part[1024];
    const int t = threadIdx.x;
    const int chunk = (n + 1023) >> 10;
    const int b = t * chunk;
    const int e = min(b + chunk, n);
    int s = 0;
    for (int i = b; i < e; i++) s += cnt[i];
    part[t] = s;
    __syncthreads();
    for (int d = 1; d < 1024; d <<= 1) {
        int v = (t >= d) ? part[t - d] : 0;
        __syncthreads();
        if (t >= d) part[t] += v;
        __syncthreads();
    }
    int run = (t == 0) ? 0 : part[t - 1];
    for (int i = b; i < e; i++) { off[i] = run; run += cnt[i]; }
    if (t == 0) off[n] = part[1023];
}

__global__ void fill2(const int* __restrict__ l_e, const int* __restrict__ c_e,
                      int* __restrict__ cur_l, int* __restrict__ cur_c,
                      int* __restrict__ src_l, int* __restrict__ src_c, int E)
{
    int i = blockIdx.x * blockDim.x + threadIdx.x;
    if (i < E) {
        int l = l_e[i], c = c_e[i];
        src_c[atomicAdd(&cur_c[c], 1)] = l;
        src_l[atomicAdd(&cur_l[l], 1)] = c;
    }
}

// ======================= gather-sum ==========================================
__global__ __launch_bounds__(256)
void gather(const float* __restrict__ msg, const int* __restrict__ off,
            const int* __restrict__ srcs, float* __restrict__ aggr, int n)
{
    int node = blockIdx.x * 8 + (threadIdx.x >> 5);
    if (node >= n) return;
    int lane = threadIdx.x & 31;
    int b = off[node], e = off[node + 1];
    float4 acc = {0.f, 0.f, 0.f, 0.f};
    for (int i = b; i < e; i++) {
        const float4 v = *((const float4*)(msg + (size_t)srcs[i] * DIM) + lane);
        acc.x += v.x; acc.y += v.y; acc.z += v.z; acc.w += v.w;
    }
    *((float4*)(aggr + (size_t)node * DIM) + lane) = acc;
}

// ---------------- GRU elementwise gate math ----------------------------------
__global__ void gru_elem(const float* __restrict__ gi, const float* __restrict__ gh,
                         const float* __restrict__ h, float* __restrict__ hnew, int N)
{
    int idx = blockIdx.x * blockDim.x + threadIdx.x;
    if (idx >= N * DIM) return;
    int row = idx >> 7, col = idx & 127;
    const float* gir = gi + (size_t)row * 3 * DIM;
    const float* ghr = gh + (size_t)row * 3 * DIM;
    float ir = gir[col], iz = gir[DIM + col], in_ = gir[2 * DIM + col];
    float hr = ghr[col], hz = ghr[DIM + col], hn  = ghr[2 * DIM + col];
    float r = fsigmoid(ir + hr);
    float z = fsigmoid(iz + hz);
    float n = ftanh(in_ + r * hn);
    hnew[idx] = (1.f - z) * n + z * h[idx];
}

// ---------------- launch ------------------------------------------------------
extern "C" void kernel_launch(void* const* d_in, const int* in_sizes, int n_in,
                              void* d_out, int out_size)
{
    const int D = DIM;
    const int E = in_sizes[2];
    const int L = in_sizes[4] / D;
    const int C = in_sizes[5] / D;

    const int*   l_edge = (const int*)d_in[2];
    const int*   c_edge = (const int*)d_in[3];
    const float* l_emb0 = (const float*)d_in[4];
    const float* c_emb0 = (const float*)d_in[5];

    const float* l2c_W0 = (const float*)d_in[6];
    const float* l2c_b0 = (const float*)d_in[7];
    const float* l2c_W1 = (const float*)d_in[8];
    const float* l2c_b1 = (const float*)d_in[9];
    const float* c2l_W0 = (const float*)d_in[10];
    const float* c2l_b0 = (const float*)d_in[11];
    const float* c2l_W1 = (const float*)d_in[12];
    const float* c2l_b1 = (const float*)d_in[13];
    const float* l2l_W0 = (const float*)d_in[14];
    const float* l2l_b0 = (const float*)d_in[15];
    const float* l2l_W1 = (const float*)d_in[16];
    const float* l2l_b1 = (const float*)d_in[17];
    const float* c_Wih  = (const float*)d_in[18];
    const float* c_Whh  = (const float*)d_in[19];
    const float* c_bih  = (const float*)d_in[20];
    const float* c_bhh  = (const float*)d_in[21];
    const float* l_Wih  = (const float*)d_in[22];
    const float* l_Whh  = (const float*)d_in[23];
    const float* l_bih  = (const float*)d_in[24];
    const float* l_bhh  = (const float*)d_in[25];

    float* out   = (float*)d_out;
    float* louts = out;                                // [9, L, D]
    float* couts = out + (size_t)(NITER + 1) * L * D;  // [9, C, D]

    float *l2c_msg, *c2l_msg, *l2l_msg, *aggr_c, *aggr_l, *gi_c, *gh_c, *gi_l, *gh_l;
    cudaGetSymbolAddress((void**)&l2c_msg, g_l2c_msg);
    cudaGetSymbolAddress((void**)&c2l_msg, g_c2l_msg);
    cudaGetSymbolAddress((void**)&l2l_msg, g_l2l_msg);
    cudaGetSymbolAddress((void**)&aggr_c,  g_aggr_c);
    cudaGetSymbolAddress((void**)&aggr_l,  g_aggr_l);
    cudaGetSymbolAddress((void**)&gi_c,    g_gi_c);
    cudaGetSymbolAddress((void**)&gh_c,    g_gh_c);
    cudaGetSymbolAddress((void**)&gi_l,    g_gi_l);
    cudaGetSymbolAddress((void**)&gh_l,    g_gh_l);

    int *cnt_c, *cnt_l, *off_c, *off_l, *cur_c, *cur_l, *src_c, *src_l;
    cudaGetSymbolAddress((void**)&cnt_c, g_cnt_c);
    cudaGetSymbolAddress((void**)&cnt_l, g_cnt_l);
    cudaGetSymbolAddress((void**)&off_c, g_off_c);
    cudaGetSymbolAddress((void**)&off_l, g_off_l);
    cudaGetSymbolAddress((void**)&cur_c, g_cur_c);
    cudaGetSymbolAddress((void**)&cur_l, g_cur_l);
    cudaGetSymbolAddress((void**)&src_c, g_src_c);
    cudaGetSymbolAddress((void**)&src_l, g_src_l);

    uint32_t *whi, *wlo;
    cudaGetSymbolAddress((void**)&whi, g_whi);
    cudaGetSymbolAddress((void**)&wlo, g_wlo);

    cudaFuncSetAttribute(mlp2_bf3, cudaFuncAttributeMaxDynamicSharedMemorySize,
                         MLP2_DSMEM);

    const int o_l2c0 = 0,      o_l2c1 = 8192,  o_c2l0 = 16384, o_c2l1 = 24576;
    const int o_l2l0 = 32768,  o_l2l1 = 40960;
    const int o_cih  = 49152,  o_chh  = 73728;
    const int o_lih  = 98304,  o_lhh  = 147456;

    // ---- pre-split weights into fragment-ordered bf16 hi/lo planes ----
    split_w<<<32, 256>>>(l2c_W0, whi + o_l2c0, wlo + o_l2c0, 8192, 64);
    split_w<<<32, 256>>>(l2c_W1, whi + o_l2c1, wlo + o_l2c1, 8192, 64);
    split_w<<<32, 256>>>(c2l_W0, whi + o_c2l0, wlo + o_c2l0, 8192, 64);
    split_w<<<32, 256>>>(c2l_W1, whi + o_c2l1, wlo + o_c2l1, 8192, 64);
    split_w<<<32, 256>>>(l2l_W0, whi + o_l2l0, wlo + o_l2l0, 8192, 64);
    split_w<<<32, 256>>>(l2l_W1, whi + o_l2l1, wlo + o_l2l1, 8192, 64);
    split_w<<<96, 256>>>(c_Wih,  whi + o_cih,  wlo + o_cih,  24576, 64);
    split_w<<<96, 256>>>(c_Whh,  whi + o_chh,  wlo + o_chh,  24576, 64);
    split_w<<<192, 256>>>(l_Wih, whi + o_lih,  wlo + o_lih,  49152, 128);
    split_w<<<96, 256>>>(l_Whh,  whi + o_lhh,  wlo + o_lhh,  24576, 64);

    // ---- CSR build (edge structure static across iterations) ----
    cudaMemsetAsync(cnt_c, 0, (size_t)C * sizeof(int));
    cudaMemsetAsync(cnt_l, 0, (size_t)L * sizeof(int));
    hist2<<<(E + 255) / 256, 256>>>(l_edge, c_edge, cnt_l, cnt_c, E);
    exscan<<<1, 1024>>>(cnt_c, off_c, C);
    exscan<<<1, 1024>>>(cnt_l, off_l, L);
    cudaMemcpyAsync(cur_c, off_c, (size_t)C * sizeof(int), cudaMemcpyDeviceToDevice);
    cudaMemcpyAsync(cur_l, off_l, (size_t)L * sizeof(int), cudaMemcpyDeviceToDevice);
    fill2<<<(E + 255) / 256, 256>>>(l_edge, c_edge, cur_l, cur_c, src_l, src_c, E);

    // iteration-0 slices = inputs
    cudaMemcpyAsync(louts, l_emb0, (size_t)L * D * sizeof(float), cudaMemcpyDeviceToDevice);
    cudaMemcpyAsync(couts, c_emb0, (size_t)C * D * sizeof(float), cudaMemcpyDeviceToDevice);

    const int gLx = (L + 127) / 128;
    const int gCx = (C + 127) / 128;
    const dim3 gC3(gCx, 3), gL3(gLx, 3);

    for (int it = 0; it < NITER; it++) {
        const float* l_prev = louts + (size_t)it * L * D;
        const float* c_prev = couts + (size_t)it * C * D;
        float* l_next = louts + (size_t)(it + 1) * L * D;
        float* c_next = couts + (size_t)(it + 1) * C * D;

        // message MLPs (fused 2-layer)
        mlp2_bf3<<<gLx, 256, MLP2_DSMEM>>>(l_prev, whi + o_l2c0, wlo + o_l2c0, l2c_b0,
                                           whi + o_l2c1, wlo + o_l2c1, l2c_b1, l2c_msg, L, 0);
        mlp2_bf3<<<gCx, 256, MLP2_DSMEM>>>(c_prev, whi + o_c2l0, wlo + o_c2l0, c2l_b0,
                                           whi + o_c2l1, wlo + o_c2l1, c2l_b1, c2l_msg, C, 0);
        mlp2_bf3<<<gLx, 256, MLP2_DSMEM>>>(l_prev, whi + o_l2l0, wlo + o_l2l0, l2l_b0,
                                           whi + o_l2l1, wlo + o_l2l1, l2l_b1, l2l_msg, L, 1);

        // clause side
        gather<<<(C + 7) / 8, 256>>>(l2c_msg, off_c, src_c, aggr_c, C);
        gemm_bf3<<<gC3, 256>>>(aggr_c, nullptr, whi + o_cih, wlo + o_cih,
                               c_bih, gi_c, C, 384, 128, 0, 0);
        gemm_bf3<<<gC3, 256>>>(c_prev, nullptr, whi + o_chh, wlo + o_chh,
                               c_bhh, gh_c, C, 384, 128, 0, 0);
        gru_elem<<<(C * D + 255) / 256, 256>>>(gi_c, gh_c, c_prev, c_next, C);

        // literal side
        gather<<<(L + 7) / 8, 256>>>(c2l_msg, off_l, src_l, aggr_l, L);
        gemm_bf3<<<gL3, 256>>>(aggr_l, l2l_msg, whi + o_lih, wlo + o_lih,
                               l_bih, gi_l, L, 384, 256, 0, 0);
        gemm_bf3<<<gL3, 256>>>(l_prev, nullptr, whi + o_lhh, wlo + o_lhh,
                               l_bhh, gh_l, L, 384, 128, 0, 0);
        gru_elem<<<(L * D + 255) / 256, 256>>>(gi_l, gh_l, l_prev, l_next, L);
    }
}